// round 10
// baseline (speedup 1.0000x reference)
#include <cuda_runtime.h>
#include <math.h>

#define CLASSES 21
#define MAXT 256
#define TPB 256
#define MAXBLOCKS 8192
#define MAXA 262144

__device__ int   g_key[MAXA];     // zero-init; argmax keys via atomicMax; reset by p2
__device__ int   g_lbl[MAXA];     // per-anchor selected label (0 = background)
__device__ float g_pc[MAXBLOCKS]; // p3 block partials (cls)
__device__ float g_pr[MAXBLOCKS]; // p2 block partials (reg)
__device__ float g_pp[MAXBLOCKS]; // p2 block partials (pos count)
__device__ int   g_count;         // zero-init; reset by p3 last block

__device__ __forceinline__ float warp_red_f(float v) {
    #pragma unroll
    for (int o = 16; o > 0; o >>= 1) v += __shfl_down_sync(0xffffffffu, v, o);
    return v;
}
__device__ __forceinline__ double warp_red_d(double v) {
    #pragma unroll
    for (int o = 16; o > 0; o >>= 1) v += __shfl_down_sync(0xffffffffu, v, o);
    return v;
}

// ---------------- Phase 1 (VERBATIM R7, proven): sliced IoU argmax via atomicMax ----------------
// Rank by r = inter/(areaA+ta): IoU = r/(1-r) is strictly increasing in r, so ordering matches.
// Key = (r_bits & ~0xFF) | (255 - t_global). Negative r -> negative key -> loses signed max.
template <int CTT>
__global__ void __launch_bounds__(TPB, 8)
retina_p1(const float4* __restrict__ anc,
          const float4* __restrict__ tb,
          int A, int Tdyn)
{
    const int t0 = blockIdx.y * (CTT > 0 ? CTT : Tdyn);

    __shared__ float4 s_neg[CTT > 0 ? CTT : MAXT];   // {tz, tw, -tx1, -ty1}
    __shared__ float  s_ta [CTT > 0 ? CTT : MAXT];

    int ccount;
    if (CTT > 0) {
        ccount = CTT;
    } else {
        ccount = Tdyn - t0;
        if (ccount > MAXT) ccount = MAXT;
    }

    for (int t = threadIdx.x; t < ccount; t += TPB) {
        float4 b = tb[t0 + t];
        s_neg[t] = make_float4(b.z, b.w, -b.x, -b.y);
        s_ta[t]  = (b.z - b.x) * (b.w - b.y);
    }
    __syncthreads();

    const int a = blockIdx.x * TPB + threadIdx.x;
    if (a >= A) return;

    const float4 an = anc[a];
    const float az  = an.z,  aw = an.w;
    const float nax = -an.x, nay = -an.y;
    const float areaA = (an.z - an.x) * (an.w - an.y);
    const int idxbase = 255 - t0;

    int best = 0;
    #pragma unroll
    for (int tt = 0; tt < (CTT > 0 ? CTT : MAXT); ++tt) {
        if (CTT == 0 && tt >= ccount) break;
        float4 q = s_neg[tt];
        float ta = s_ta[tt];
        float m1 = fminf(az,  q.x);
        float m2 = fminf(aw,  q.y);
        float n1 = fminf(nax, q.z);          // = -max(ax, tx1)
        float n2 = fminf(nay, q.w);          // = -max(ay, ty1)
        float w  = fmaxf(m1 + n1, 0.f);
        float h  = m2 + n2;
        float inter = w * h;                 // <=0 never wins (key <= 0)
        float S  = areaA + ta;               // RCP off the min/max chain
        float r  = __fdividef(inter, S);     // rank-equivalent to IoU
        int key = (__float_as_int(r) & 0xFFFFFF00) | (idxbase - tt);
        best = max(best, key);
    }
    atomicMax(&g_key[a], best);              // deterministic merge
}

// ---------------- Phase 2 (light): decode, exact IoU, regression, label write ----------------
__global__ void __launch_bounds__(TPB)
retina_p2(const float4* __restrict__ box,
          const float4* __restrict__ anc,
          const float4* __restrict__ tb,
          const int* __restrict__ tl,
          int A, int T)
{
    __shared__ float4 s_org[MAXT];
    __shared__ float  s_ta[MAXT];
    __shared__ int    s_tl[MAXT];

    for (int t = threadIdx.x; t < T; t += TPB) {
        float4 b = tb[t];
        s_org[t] = b;
        s_ta[t]  = (b.z - b.x) * (b.w - b.y);
        s_tl[t]  = tl[t];
    }
    __syncthreads();

    const int a = blockIdx.x * TPB + threadIdx.x;
    float reg_sum = 0.f, posf = 0.f;

    if (a < A) {
        int key = g_key[a];
        g_key[a] = 0;                         // reset for next run/replay
        int tsel = 255 - (key & 0xFF);
        if (tsel >= T) tsel = 0;              // all-zero corner: argmax = 0, pos = false

        float4 an = anc[a];
        float4 tg = s_org[tsel];
        float areaA = (an.z - an.x) * (an.w - an.y);
        float w = fmaxf(fminf(an.z, tg.z) - fmaxf(an.x, tg.x), 0.f);
        float h = fmaxf(fminf(an.w, tg.w) - fmaxf(an.y, tg.y), 0.f);
        float inter = w * h;
        float uni   = areaA + s_ta[tsel] - inter;
        float iou   = __fdiv_rn(inter, fmaxf(uni, 1e-8f));
        const bool pos = (iou >= 0.5f);
        posf = pos ? 1.f : 0.f;
        g_lbl[a] = pos ? s_tl[tsel] : 0;      // background -> class 0 (one_hot(0))

        if (pos) {
            float4 bp = box[a];
            float awx = an.z - an.x, awy = an.w - an.y;
            float acx = (an.x + an.z) * 0.5f, acy = (an.y + an.w) * 0.5f;

            float ep0 = __fdiv_rn((bp.x + bp.z) * 0.5f - acx, awx);
            float ep1 = __fdiv_rn((bp.y + bp.w) * 0.5f - acy, awy);
            float ep2 = logf(__fdiv_rn(bp.z - bp.x, awx));
            float ep3 = logf(__fdiv_rn(bp.w - bp.y, awy));

            float et0 = __fdiv_rn((tg.x + tg.z) * 0.5f - acx, awx);
            float et1 = __fdiv_rn((tg.y + tg.w) * 0.5f - acy, awy);
            float et2 = logf(__fdiv_rn(tg.z - tg.x, awx));
            float et3 = logf(__fdiv_rn(tg.w - tg.y, awy));

            float d;
            d = fabsf(ep0 - et0); reg_sum += (d < 1.f) ? 0.5f * d * d : d - 0.5f;
            d = fabsf(ep1 - et1); reg_sum += (d < 1.f) ? 0.5f * d * d : d - 0.5f;
            d = fabsf(ep2 - et2); reg_sum += (d < 1.f) ? 0.5f * d * d : d - 0.5f;
            d = fabsf(ep3 - et3); reg_sum += (d < 1.f) ? 0.5f * d * d : d - 0.5f;
        }
    }

    __shared__ float red_r[8], red_p[8];
    float vr = warp_red_f(reg_sum);
    float vp = warp_red_f(posf);
    int wid = threadIdx.x >> 5, lid = threadIdx.x & 31;
    if (lid == 0) { red_r[wid] = vr; red_p[wid] = vp; }
    __syncthreads();
    if (wid == 0) {
        float r2 = (lid < 8) ? red_r[lid] : 0.f;
        float p2 = (lid < 8) ? red_p[lid] : 0.f;
        r2 = warp_red_f(r2);
        p2 = warp_red_f(p2);
        if (lid == 0) { g_pr[blockIdx.x] = r2; g_pp[blockIdx.x] = p2; }
    }
}

// ---------------- Phase 3: coalesced element-wise focal loss + final combine ----------------
__global__ void __launch_bounds__(TPB)
retina_p3(const float* __restrict__ cls,
          float* __restrict__ out,
          int N, int grid2)
{
    const int e0 = (blockIdx.x * TPB + threadIdx.x) * 4;
    float acc = 0.f;

    if (e0 + 3 < N) {
        float4 v = *reinterpret_cast<const float4*>(cls + e0);
        float xs[4] = {v.x, v.y, v.z, v.w};
        #pragma unroll
        for (int k = 0; k < 4; ++k) {
            int e = e0 + k;
            int a = (int)((unsigned)e / 21u);
            int c = e - a * 21;
            bool tgt = (c == g_lbl[a]);
            float x = xs[k];
            float z = tgt ? x : -x;
            float ex = __expf(-fabsf(x));          // = exp(-|z|)
            float l1p = __logf(1.f + ex);
            float rc  = __fdividef(1.f, 1.f + ex);
            float ce  = l1p + fmaxf(-z, 0.f);      // softplus(-z)
            float q   = (z >= 0.f) ? ex * rc : rc; // sigmoid(-z) = 1 - pt
            float alpha = tgt ? 0.25f : 0.75f;
            acc += alpha * q * q * ce;
        }
    } else {
        for (int e = e0; e < N; ++e) {
            int a = (int)((unsigned)e / 21u);
            int c = e - a * 21;
            bool tgt = (c == g_lbl[a]);
            float x = cls[e];
            float z = tgt ? x : -x;
            float ex = __expf(-fabsf(x));
            float l1p = __logf(1.f + ex);
            float rc  = __fdividef(1.f, 1.f + ex);
            float ce  = l1p + fmaxf(-z, 0.f);
            float q   = (z >= 0.f) ? ex * rc : rc;
            float alpha = tgt ? 0.25f : 0.75f;
            acc += alpha * q * q * ce;
        }
    }

    __shared__ float red_c[8];
    float vc = warp_red_f(acc);
    int wid = threadIdx.x >> 5, lid = threadIdx.x & 31;
    if (lid == 0) red_c[wid] = vc;
    __syncthreads();
    if (wid == 0) {
        float c2 = (lid < 8) ? red_c[lid] : 0.f;
        c2 = warp_red_f(c2);
        if (lid == 0) g_pc[blockIdx.x] = c2;
    }

    __shared__ int s_last;
    if (threadIdx.x == 0) {
        __threadfence();
        int prev = atomicAdd(&g_count, 1);
        s_last = (prev == (int)gridDim.x - 1) ? 1 : 0;
    }
    __syncthreads();
    if (s_last) {
        double c = 0.0, r = 0.0, p = 0.0;
        for (int i = threadIdx.x; i < (int)gridDim.x; i += TPB) c += (double)g_pc[i];
        for (int i = threadIdx.x; i < grid2; i += TPB) {
            r += (double)g_pr[i];
            p += (double)g_pp[i];
        }
        c = warp_red_d(c);
        r = warp_red_d(r);
        p = warp_red_d(p);
        __shared__ double sc[8], sr[8], sp[8];
        if (lid == 0) { sc[wid] = c; sr[wid] = r; sp[wid] = p; }
        __syncthreads();
        if (threadIdx.x == 0) {
            double tc = 0.0, tr = 0.0, tp = 0.0;
            #pragma unroll
            for (int i = 0; i < 8; ++i) { tc += sc[i]; tr += sr[i]; tp += sp[i]; }
            float pos_cnt = (float)tp;
            float norm = fmaxf(pos_cnt, 1.f);
            float cls_loss = (float)tc / norm;
            float reg_loss = (pos_cnt > 0.f) ? ((float)tr / (norm * 4.f)) : 0.f;
            out[0] = cls_loss + reg_loss;
            out[1] = cls_loss;
            out[2] = reg_loss;
            g_count = 0;
        }
    }
}

extern "C" void kernel_launch(void* const* d_in, const int* in_sizes, int n_in,
                              void* d_out, int out_size)
{
    const float*  cls = (const float*)d_in[0];
    const float4* box = (const float4*)d_in[1];
    const float4* anc = (const float4*)d_in[2];
    const float4* tb  = (const float4*)d_in[3];
    const int*    tl  = (const int*)d_in[4];
    float* out = (float*)d_out;

    int A = in_sizes[2] / 4;       // flattened anchors (B*A)
    int T = in_sizes[4];           // flattened targets (B*T)
    int N = in_sizes[0];           // A * CLASSES
    if (T > 255) T = 255;
    if (A > MAXA) A = MAXA;

    int gx12 = (A + TPB - 1) / TPB;               // p1.x / p2 blocks -> 768
    int gx3  = (N + TPB * 4 - 1) / (TPB * 4);     // p3 blocks -> 4032
    if (gx12 > MAXBLOCKS / 2) gx12 = MAXBLOCKS / 2;
    if (gx3 > MAXBLOCKS) gx3 = MAXBLOCKS;

    if (T == 200) {
        dim3 g1(gx12, 4);                         // 4 slices x 50 targets
        retina_p1<50><<<g1, TPB>>>(anc, tb, A, T);
    } else {
        dim3 g1(gx12, 1);
        retina_p1<0><<<g1, TPB>>>(anc, tb, A, T);
    }
    retina_p2<<<gx12, TPB>>>(box, anc, tb, tl, A, T);
    retina_p3<<<gx3, TPB>>>(cls, out, N, gx12);
}

// round 11
// speedup vs baseline: 1.4917x; 1.4917x over previous
#include <cuda_runtime.h>
#include <math.h>

#define CLASSES 21
#define MAXT 256
#define TPB 256
#define MAXBLOCKS 8192
#define MAXA 262144

__device__ int   g_key[MAXA];      // zero-init; argmax keys via atomicMax; reset by p2
__device__ float g_pc[MAXBLOCKS];  // p3 block partials (background focal, pre-scaled by 0.75)
__device__ float g_pcor[MAXBLOCKS];// p2 block partials (focal correction)
__device__ float g_pr[MAXBLOCKS];  // p2 block partials (reg)
__device__ float g_pp[MAXBLOCKS];  // p2 block partials (pos count)
__device__ int   g_count;          // zero-init; reset by p3 last block

__device__ __forceinline__ float warp_red_f(float v) {
    #pragma unroll
    for (int o = 16; o > 0; o >>= 1) v += __shfl_down_sync(0xffffffffu, v, o);
    return v;
}
__device__ __forceinline__ double warp_red_d(double v) {
    #pragma unroll
    for (int o = 16; o > 0; o >>= 1) v += __shfl_down_sync(0xffffffffu, v, o);
    return v;
}

// ---------------- Phase 1 (VERBATIM R10, proven): sliced IoU argmax via atomicMax ----------------
// Rank by r = inter/(areaA+ta): IoU = r/(1-r) strictly increasing in r => same ordering.
// Key = (r_bits & ~0xFF) | (255 - t_global). Negative r -> negative key -> loses signed max.
template <int CTT>
__global__ void __launch_bounds__(TPB, 8)
retina_p1(const float4* __restrict__ anc,
          const float4* __restrict__ tb,
          int A, int Tdyn)
{
    const int t0 = blockIdx.y * (CTT > 0 ? CTT : Tdyn);

    __shared__ float4 s_neg[CTT > 0 ? CTT : MAXT];   // {tz, tw, -tx1, -ty1}
    __shared__ float  s_ta [CTT > 0 ? CTT : MAXT];

    int ccount;
    if (CTT > 0) {
        ccount = CTT;
    } else {
        ccount = Tdyn - t0;
        if (ccount > MAXT) ccount = MAXT;
    }

    for (int t = threadIdx.x; t < ccount; t += TPB) {
        float4 b = tb[t0 + t];
        s_neg[t] = make_float4(b.z, b.w, -b.x, -b.y);
        s_ta[t]  = (b.z - b.x) * (b.w - b.y);
    }
    __syncthreads();

    const int a = blockIdx.x * TPB + threadIdx.x;
    if (a >= A) return;

    const float4 an = anc[a];
    const float az  = an.z,  aw = an.w;
    const float nax = -an.x, nay = -an.y;
    const float areaA = (an.z - an.x) * (an.w - an.y);
    const int idxbase = 255 - t0;

    int best = 0;
    #pragma unroll
    for (int tt = 0; tt < (CTT > 0 ? CTT : MAXT); ++tt) {
        if (CTT == 0 && tt >= ccount) break;
        float4 q = s_neg[tt];
        float ta = s_ta[tt];
        float m1 = fminf(az,  q.x);
        float m2 = fminf(aw,  q.y);
        float n1 = fminf(nax, q.z);          // = -max(ax, tx1)
        float n2 = fminf(nay, q.w);          // = -max(ay, ty1)
        float w  = fmaxf(m1 + n1, 0.f);
        float h  = m2 + n2;
        float inter = w * h;                 // <=0 never wins (key <= 0)
        float S  = areaA + ta;               // RCP off the min/max chain
        float r  = __fdividef(inter, S);     // rank-equivalent to IoU
        int key = (__float_as_int(r) & 0xFFFFFF00) | (idxbase - tt);
        best = max(best, key);
    }
    atomicMax(&g_key[a], best);              // deterministic merge
}

// ---- Phase 2: decode winner, exact IoU, regression + per-anchor focal CORRECTION ----
__global__ void __launch_bounds__(TPB)
retina_p2(const float* __restrict__ cls,
          const float4* __restrict__ box,
          const float4* __restrict__ anc,
          const float4* __restrict__ tb,
          const int* __restrict__ tl,
          int A, int T)
{
    __shared__ float4 s_org[MAXT];
    __shared__ float  s_ta[MAXT];
    __shared__ int    s_tl[MAXT];

    for (int t = threadIdx.x; t < T; t += TPB) {
        float4 b = tb[t];
        s_org[t] = b;
        s_ta[t]  = (b.z - b.x) * (b.w - b.y);
        s_tl[t]  = tl[t];
    }
    __syncthreads();

    const int a = blockIdx.x * TPB + threadIdx.x;
    float reg_sum = 0.f, posf = 0.f, cor_sum = 0.f;

    if (a < A) {
        int key = g_key[a];
        g_key[a] = 0;                         // reset for next run/replay
        int tsel = 255 - (key & 0xFF);
        if (tsel >= T) tsel = 0;              // all-zero corner: argmax = 0, pos = false

        float4 an = anc[a];
        float4 tg = s_org[tsel];
        float areaA = (an.z - an.x) * (an.w - an.y);
        float w = fmaxf(fminf(an.z, tg.z) - fmaxf(an.x, tg.x), 0.f);
        float h = fmaxf(fminf(an.w, tg.w) - fmaxf(an.y, tg.y), 0.f);
        float inter = w * h;
        float uni   = areaA + s_ta[tsel] - inter;
        float iou   = __fdiv_rn(inter, fmaxf(uni, 1e-8f));
        const bool pos = (iou >= 0.5f);
        posf = pos ? 1.f : 0.f;
        const int lbl = pos ? s_tl[tsel] : 0; // background -> class 0 (one_hot(0))

        // focal correction for the single target class (p3 sums ALL classes as background)
        {
            float x  = cls[(size_t)a * CLASSES + lbl];
            float ex = __expf(-fabsf(x));
            float op = 1.f + ex;
            float rc = __fdividef(1.f, op);
            float l1p = __logf(op);
            float sp_b = l1p + fmaxf(x, 0.f);           // softplus(x)   (ce, t=0)
            float sg_p = (x >= 0.f) ? rc : ex * rc;     // sigmoid(x)    (1-pt, t=0)
            float sp_p = l1p + fmaxf(-x, 0.f);          // softplus(-x)  (ce, t=1)
            float sg_n = (x >= 0.f) ? ex * rc : rc;     // sigmoid(-x)   (1-pt, t=1)
            cor_sum = 0.25f * sg_n * sg_n * sp_p - 0.75f * sg_p * sg_p * sp_b;
        }

        if (pos) {
            float4 bp = box[a];
            float awx = an.z - an.x, awy = an.w - an.y;
            float acx = (an.x + an.z) * 0.5f, acy = (an.y + an.w) * 0.5f;

            float ep0 = __fdiv_rn((bp.x + bp.z) * 0.5f - acx, awx);
            float ep1 = __fdiv_rn((bp.y + bp.w) * 0.5f - acy, awy);
            float ep2 = logf(__fdiv_rn(bp.z - bp.x, awx));
            float ep3 = logf(__fdiv_rn(bp.w - bp.y, awy));

            float et0 = __fdiv_rn((tg.x + tg.z) * 0.5f - acx, awx);
            float et1 = __fdiv_rn((tg.y + tg.w) * 0.5f - acy, awy);
            float et2 = logf(__fdiv_rn(tg.z - tg.x, awx));
            float et3 = logf(__fdiv_rn(tg.w - tg.y, awy));

            float d;
            d = fabsf(ep0 - et0); reg_sum += (d < 1.f) ? 0.5f * d * d : d - 0.5f;
            d = fabsf(ep1 - et1); reg_sum += (d < 1.f) ? 0.5f * d * d : d - 0.5f;
            d = fabsf(ep2 - et2); reg_sum += (d < 1.f) ? 0.5f * d * d : d - 0.5f;
            d = fabsf(ep3 - et3); reg_sum += (d < 1.f) ? 0.5f * d * d : d - 0.5f;
        }
    }

    __shared__ float red_r[8], red_p[8], red_k[8];
    float vr = warp_red_f(reg_sum);
    float vp = warp_red_f(posf);
    float vk = warp_red_f(cor_sum);
    int wid = threadIdx.x >> 5, lid = threadIdx.x & 31;
    if (lid == 0) { red_r[wid] = vr; red_p[wid] = vp; red_k[wid] = vk; }
    __syncthreads();
    if (wid == 0) {
        float r2 = (lid < 8) ? red_r[lid] : 0.f;
        float p2 = (lid < 8) ? red_p[lid] : 0.f;
        float k2 = (lid < 8) ? red_k[lid] : 0.f;
        r2 = warp_red_f(r2);
        p2 = warp_red_f(p2);
        k2 = warp_red_f(k2);
        if (lid == 0) { g_pr[blockIdx.x] = r2; g_pp[blockIdx.x] = p2; g_pcor[blockIdx.x] = k2; }
    }
}

// ---- Phase 3: pure background focal over cls (coalesced, no lbl dependency) + final combine ----
__global__ void __launch_bounds__(TPB)
retina_p3(const float* __restrict__ cls,
          float* __restrict__ out,
          int N, int grid2)
{
    const int e0 = (blockIdx.x * TPB + threadIdx.x) * 4;
    float acc = 0.f;

    if (e0 + 3 < N) {
        float4 v = *reinterpret_cast<const float4*>(cls + e0);
        float xs[4] = {v.x, v.y, v.z, v.w};
        #pragma unroll
        for (int k = 0; k < 4; ++k) {
            float x = xs[k];
            float ex = __expf(-fabsf(x));
            float op = 1.f + ex;
            float rc = __fdividef(1.f, op);
            float l1p = __logf(op);
            float sp  = l1p + fmaxf(x, 0.f);            // softplus(x)  (ce, t=0)
            float sg  = (x >= 0.f) ? rc : ex * rc;      // sigmoid(x)   (1-pt, t=0)
            acc += sg * sg * sp;
        }
    } else {
        for (int e = e0; e < N; ++e) {
            float x = cls[e];
            float ex = __expf(-fabsf(x));
            float op = 1.f + ex;
            float rc = __fdividef(1.f, op);
            float l1p = __logf(op);
            float sp  = l1p + fmaxf(x, 0.f);
            float sg  = (x >= 0.f) ? rc : ex * rc;
            acc += sg * sg * sp;
        }
    }

    __shared__ float red_c[8];
    float vc = warp_red_f(acc);
    int wid = threadIdx.x >> 5, lid = threadIdx.x & 31;
    if (lid == 0) red_c[wid] = vc;
    __syncthreads();
    if (wid == 0) {
        float c2 = (lid < 8) ? red_c[lid] : 0.f;
        c2 = warp_red_f(c2);
        if (lid == 0) g_pc[blockIdx.x] = 0.75f * c2;    // alpha_bg folded here
    }

    __shared__ int s_last;
    if (threadIdx.x == 0) {
        __threadfence();
        int prev = atomicAdd(&g_count, 1);
        s_last = (prev == (int)gridDim.x - 1) ? 1 : 0;
    }
    __syncthreads();
    if (s_last) {
        double c = 0.0, r = 0.0, p = 0.0;
        for (int i = threadIdx.x; i < (int)gridDim.x; i += TPB) c += (double)g_pc[i];
        for (int i = threadIdx.x; i < grid2; i += TPB) {
            c += (double)g_pcor[i];
            r += (double)g_pr[i];
            p += (double)g_pp[i];
        }
        c = warp_red_d(c);
        r = warp_red_d(r);
        p = warp_red_d(p);
        __shared__ double sc[8], sr[8], sp[8];
        if (lid == 0) { sc[wid] = c; sr[wid] = r; sp[wid] = p; }
        __syncthreads();
        if (threadIdx.x == 0) {
            double tc = 0.0, tr = 0.0, tp = 0.0;
            #pragma unroll
            for (int i = 0; i < 8; ++i) { tc += sc[i]; tr += sr[i]; tp += sp[i]; }
            float pos_cnt = (float)tp;
            float norm = fmaxf(pos_cnt, 1.f);
            float cls_loss = (float)tc / norm;
            float reg_loss = (pos_cnt > 0.f) ? ((float)tr / (norm * 4.f)) : 0.f;
            out[0] = cls_loss + reg_loss;
            out[1] = cls_loss;
            out[2] = reg_loss;
            g_count = 0;
        }
    }
}

extern "C" void kernel_launch(void* const* d_in, const int* in_sizes, int n_in,
                              void* d_out, int out_size)
{
    const float*  cls = (const float*)d_in[0];
    const float4* box = (const float4*)d_in[1];
    const float4* anc = (const float4*)d_in[2];
    const float4* tb  = (const float4*)d_in[3];
    const int*    tl  = (const int*)d_in[4];
    float* out = (float*)d_out;

    int A = in_sizes[2] / 4;       // flattened anchors (B*A)
    int T = in_sizes[4];           // flattened targets (B*T)
    int N = in_sizes[0];           // A * CLASSES
    if (T > 255) T = 255;
    if (A > MAXA) A = MAXA;

    int gx12 = (A + TPB - 1) / TPB;               // p1.x / p2 blocks -> 768
    int gx3  = (N + TPB * 4 - 1) / (TPB * 4);     // p3 blocks -> 4032
    if (gx12 > MAXBLOCKS / 2) gx12 = MAXBLOCKS / 2;
    if (gx3 > MAXBLOCKS) gx3 = MAXBLOCKS;

    if (T == 200) {
        dim3 g1(gx12, 4);                         // 4 slices x 50 targets
        retina_p1<50><<<g1, TPB>>>(anc, tb, A, T);
    } else {
        dim3 g1(gx12, 1);
        retina_p1<0><<<g1, TPB>>>(anc, tb, A, T);
    }
    retina_p2<<<gx12, TPB>>>(cls, box, anc, tb, tl, A, T);
    retina_p3<<<gx3, TPB>>>(cls, out, N, gx12);
}

// round 13
// speedup vs baseline: 1.6353x; 1.0963x over previous
#include <cuda_runtime.h>
#include <math.h>

#define CLASSES 21
#define MAXT 256
#define TPB 256
#define MAXBLOCKS 8192
#define MAXA 262144
#define FEL 6                       // focal elements per p1 thread (6*786432 >= 4.13M)

__device__ int   g_key[MAXA];       // zero-init; argmax keys via atomicMax; reset by p2
__device__ float g_pc[MAXBLOCKS];   // p1 block partials (background focal, pre-scaled 0.75)
__device__ float g_pcor[MAXBLOCKS]; // p2 block partials (focal correction)
__device__ float g_pr[MAXBLOCKS];   // p2 block partials (reg)
__device__ float g_pp[MAXBLOCKS];   // p2 block partials (pos count)
__device__ int   g_count;           // zero-init; reset by p2 last block

__device__ __forceinline__ float warp_red_f(float v) {
    #pragma unroll
    for (int o = 16; o > 0; o >>= 1) v += __shfl_down_sync(0xffffffffu, v, o);
    return v;
}
__device__ __forceinline__ double warp_red_d(double v) {
    #pragma unroll
    for (int o = 16; o > 0; o >>= 1) v += __shfl_down_sync(0xffffffffu, v, o);
    return v;
}

// backgound-focal term for one logit; returns sg^2 * softplus(x) (alpha applied later)
__device__ __forceinline__ float focal_bg(float x) {
    float ex = __expf(-fabsf(x));
    float op = 1.f + ex;
    float rc = __fdividef(1.f, op);
    float l1p = __logf(op);
    float sp  = l1p + fmaxf(x, 0.f);           // softplus(x)   (ce, t=0)
    float sg  = (x >= 0.f) ? rc : ex * rc;     // sigmoid(x)    (1-pt, t=0)
    return sg * sg * sp;
}

// ---------------- K1: sliced IoU argmax (R10-proven math) + background focal fused ----------------
template <int CTT>
__global__ void __launch_bounds__(TPB, 6)
retina_p1f(const float* __restrict__ cls,
           const float4* __restrict__ anc,
           const float4* __restrict__ tb,
           int A, int Tdyn, int N)
{
    const int t0 = blockIdx.y * (CTT > 0 ? CTT : Tdyn);
    const int fb = blockIdx.y * gridDim.x + blockIdx.x;        // flat block id
    const int total = gridDim.x * gridDim.y * TPB;
    const int tid_flat = fb * TPB + threadIdx.x;

    // ---- issue 6 independent focal loads up front (latency hidden by everything below) ----
    float xs[FEL];
    #pragma unroll
    for (int k = 0; k < FEL; ++k) {
        int e = tid_flat + k * total;
        xs[k] = (e < N) ? cls[e] : -100.f;     // -100 contributes exactly 0 to focal_bg
    }

    __shared__ float4 s_neg[CTT > 0 ? CTT : MAXT];   // {tz, tw, -tx1, -ty1}
    __shared__ float  s_ta [CTT > 0 ? CTT : MAXT];

    int ccount;
    if (CTT > 0) {
        ccount = CTT;
    } else {
        ccount = Tdyn - t0;
        if (ccount > MAXT) ccount = MAXT;
    }

    for (int t = threadIdx.x; t < ccount; t += TPB) {
        float4 b = tb[t0 + t];
        s_neg[t] = make_float4(b.z, b.w, -b.x, -b.y);
        s_ta[t]  = (b.z - b.x) * (b.w - b.y);
    }
    __syncthreads();

    // ---- focal math (loads have landed; frees xs regs before the hot loop) ----
    float facc = 0.f;
    #pragma unroll
    for (int k = 0; k < FEL; ++k) facc += focal_bg(xs[k]);

    // ---- IoU argmax over this slice (verbatim R10 math) ----
    const int a = blockIdx.x * TPB + threadIdx.x;
    if (a < A) {
        const float4 an = anc[a];
        const float az  = an.z,  aw = an.w;
        const float nax = -an.x, nay = -an.y;
        const float areaA = (an.z - an.x) * (an.w - an.y);
        const int idxbase = 255 - t0;

        int best = 0;
        #pragma unroll
        for (int tt = 0; tt < (CTT > 0 ? CTT : MAXT); ++tt) {
            if (CTT == 0 && tt >= ccount) break;
            float4 q = s_neg[tt];
            float ta = s_ta[tt];
            float m1 = fminf(az,  q.x);
            float m2 = fminf(aw,  q.y);
            float n1 = fminf(nax, q.z);          // = -max(ax, tx1)
            float n2 = fminf(nay, q.w);          // = -max(ay, ty1)
            float w  = fmaxf(m1 + n1, 0.f);
            float h  = m2 + n2;
            float inter = w * h;                 // <=0 never wins (key <= 0)
            float S  = areaA + ta;               // RCP off the min/max chain
            float r  = __fdividef(inter, S);     // rank-equivalent to IoU
            int key = (__float_as_int(r) & 0xFFFFFF00) | (idxbase - tt);
            best = max(best, key);
        }
        atomicMax(&g_key[a], best);              // deterministic merge
    }

    // ---- block-reduce focal partial ----
    __shared__ float red_c[8];
    float vc = warp_red_f(facc);
    int wid = threadIdx.x >> 5, lid = threadIdx.x & 31;
    if (lid == 0) red_c[wid] = vc;
    __syncthreads();
    if (wid == 0) {
        float c2 = (lid < 8) ? red_c[lid] : 0.f;
        c2 = warp_red_f(c2);
        if (lid == 0) g_pc[fb] = 0.75f * c2;     // alpha_bg folded here
    }
}

// ---- K2: decode winner, exact IoU, focal correction, regression, FINAL combine ----
__global__ void __launch_bounds__(TPB)
retina_p2f(const float* __restrict__ cls,
           const float4* __restrict__ box,
           const float4* __restrict__ anc,
           const float4* __restrict__ tb,
           const int* __restrict__ tl,
           float* __restrict__ out,
           int A, int T, int nP1Blocks)
{
    __shared__ float4 s_org[MAXT];
    __shared__ float  s_ta[MAXT];
    __shared__ int    s_tl[MAXT];

    for (int t = threadIdx.x; t < T; t += TPB) {
        float4 b = tb[t];
        s_org[t] = b;
        s_ta[t]  = (b.z - b.x) * (b.w - b.y);
        s_tl[t]  = tl[t];
    }
    __syncthreads();

    const int a = blockIdx.x * TPB + threadIdx.x;
    float reg_sum = 0.f, posf = 0.f, cor_sum = 0.f;

    if (a < A) {
        int key = g_key[a];
        g_key[a] = 0;                         // reset for next run/replay
        int tsel = 255 - (key & 0xFF);
        if (tsel >= T) tsel = 0;              // all-zero corner: argmax = 0, pos = false

        float4 an = anc[a];
        float4 tg = s_org[tsel];
        float areaA = (an.z - an.x) * (an.w - an.y);
        float w = fmaxf(fminf(an.z, tg.z) - fmaxf(an.x, tg.x), 0.f);
        float h = fmaxf(fminf(an.w, tg.w) - fmaxf(an.y, tg.y), 0.f);
        float inter = w * h;
        float uni   = areaA + s_ta[tsel] - inter;
        float iou   = __fdiv_rn(inter, fmaxf(uni, 1e-8f));
        const bool pos = (iou >= 0.5f);
        posf = pos ? 1.f : 0.f;
        const int lbl = pos ? s_tl[tsel] : 0; // background -> class 0 (one_hot(0))

        // focal correction for the single target class (K1 summed ALL classes as bg)
        {
            float x  = cls[(size_t)a * CLASSES + lbl];
            float ex = __expf(-fabsf(x));
            float op = 1.f + ex;
            float rc = __fdividef(1.f, op);
            float l1p = __logf(op);
            float sp_b = l1p + fmaxf(x, 0.f);           // softplus(x)   (ce, t=0)
            float sg_p = (x >= 0.f) ? rc : ex * rc;     // sigmoid(x)    (1-pt, t=0)
            float sp_p = l1p + fmaxf(-x, 0.f);          // softplus(-x)  (ce, t=1)
            float sg_n = (x >= 0.f) ? ex * rc : rc;     // sigmoid(-x)   (1-pt, t=1)
            cor_sum = 0.25f * sg_n * sg_n * sp_p - 0.75f * sg_p * sg_p * sp_b;
        }

        if (pos) {
            float4 bp = box[a];
            float awx = an.z - an.x, awy = an.w - an.y;
            float acx = (an.x + an.z) * 0.5f, acy = (an.y + an.w) * 0.5f;

            float ep0 = __fdiv_rn((bp.x + bp.z) * 0.5f - acx, awx);
            float ep1 = __fdiv_rn((bp.y + bp.w) * 0.5f - acy, awy);
            float ep2 = logf(__fdiv_rn(bp.z - bp.x, awx));
            float ep3 = logf(__fdiv_rn(bp.w - bp.y, awy));

            float et0 = __fdiv_rn((tg.x + tg.z) * 0.5f - acx, awx);
            float et1 = __fdiv_rn((tg.y + tg.w) * 0.5f - acy, awy);
            float et2 = logf(__fdiv_rn(tg.z - tg.x, awx));
            float et3 = logf(__fdiv_rn(tg.w - tg.y, awy));

            float d;
            d = fabsf(ep0 - et0); reg_sum += (d < 1.f) ? 0.5f * d * d : d - 0.5f;
            d = fabsf(ep1 - et1); reg_sum += (d < 1.f) ? 0.5f * d * d : d - 0.5f;
            d = fabsf(ep2 - et2); reg_sum += (d < 1.f) ? 0.5f * d * d : d - 0.5f;
            d = fabsf(ep3 - et3); reg_sum += (d < 1.f) ? 0.5f * d * d : d - 0.5f;
        }
    }

    __shared__ float red_r[8], red_p[8], red_k[8];
    float vr = warp_red_f(reg_sum);
    float vp = warp_red_f(posf);
    float vk = warp_red_f(cor_sum);
    int wid = threadIdx.x >> 5, lid = threadIdx.x & 31;
    if (lid == 0) { red_r[wid] = vr; red_p[wid] = vp; red_k[wid] = vk; }
    __syncthreads();
    if (wid == 0) {
        float r2 = (lid < 8) ? red_r[lid] : 0.f;
        float p2 = (lid < 8) ? red_p[lid] : 0.f;
        float k2 = (lid < 8) ? red_k[lid] : 0.f;
        r2 = warp_red_f(r2);
        p2 = warp_red_f(p2);
        k2 = warp_red_f(k2);
        if (lid == 0) { g_pr[blockIdx.x] = r2; g_pp[blockIdx.x] = p2; g_pcor[blockIdx.x] = k2; }
    }

    // ---- last-block final combine ----
    __shared__ int s_last;
    if (threadIdx.x == 0) {
        __threadfence();
        int prev = atomicAdd(&g_count, 1);
        s_last = (prev == (int)gridDim.x - 1) ? 1 : 0;
    }
    __syncthreads();
    if (s_last) {
        double c = 0.0, r = 0.0, p = 0.0;
        for (int i = threadIdx.x; i < nP1Blocks; i += TPB) c += (double)g_pc[i];
        for (int i = threadIdx.x; i < (int)gridDim.x; i += TPB) {
            c += (double)g_pcor[i];
            r += (double)g_pr[i];
            p += (double)g_pp[i];
        }
        c = warp_red_d(c);
        r = warp_red_d(r);
        p = warp_red_d(p);
        __shared__ double sc[8], sr[8], sp[8];
        if (lid == 0) { sc[wid] = c; sr[wid] = r; sp[wid] = p; }
        __syncthreads();
        if (threadIdx.x == 0) {
            double tc = 0.0, tr = 0.0, tp = 0.0;
            #pragma unroll
            for (int i = 0; i < 8; ++i) { tc += sc[i]; tr += sr[i]; tp += sp[i]; }
            float pos_cnt = (float)tp;
            float norm = fmaxf(pos_cnt, 1.f);
            float cls_loss = (float)tc / norm;
            float reg_loss = (pos_cnt > 0.f) ? ((float)tr / (norm * 4.f)) : 0.f;
            out[0] = cls_loss + reg_loss;
            out[1] = cls_loss;
            out[2] = reg_loss;
            g_count = 0;
        }
    }
}

extern "C" void kernel_launch(void* const* d_in, const int* in_sizes, int n_in,
                              void* d_out, int out_size)
{
    const float*  cls = (const float*)d_in[0];
    const float4* box = (const float4*)d_in[1];
    const float4* anc = (const float4*)d_in[2];
    const float4* tb  = (const float4*)d_in[3];
    const int*    tl  = (const int*)d_in[4];
    float* out = (float*)d_out;

    int A = in_sizes[2] / 4;       // flattened anchors (B*A)
    int T = in_sizes[4];           // flattened targets (B*T)
    int N = in_sizes[0];           // A * CLASSES
    if (T > 255) T = 255;
    if (A > MAXA) A = MAXA;

    int gx = (A + TPB - 1) / TPB;                 // 768
    if (gx > MAXBLOCKS / 4) gx = MAXBLOCKS / 4;   // flat p1 blocks must fit MAXBLOCKS

    if (T == 200) {
        dim3 g1(gx, 4);                           // 4 slices x 50 targets -> 3072 blocks
        retina_p1f<50><<<g1, TPB>>>(cls, anc, tb, A, T, N);
        retina_p2f<<<gx, TPB>>>(cls, box, anc, tb, tl, out, A, T, gx * 4);
    } else {
        dim3 g1(gx, 1);
        retina_p1f<0><<<g1, TPB>>>(cls, anc, tb, A, T, N);
        retina_p2f<<<gx, TPB>>>(cls, box, anc, tb, tl, out, A, T, gx);
    }
}

// round 14
// speedup vs baseline: 1.7696x; 1.0821x over previous
#include <cuda_runtime.h>
#include <math.h>

#define CLASSES 21
#define MAXT 256
#define TPB 256
#define MAXBLOCKS 8192
#define MAXA 262144

__device__ int   g_key[MAXA];      // zero-init; argmax keys via atomicMax; reset by p2
__device__ float g_pc[MAXBLOCKS];  // p2 block partials (cls)
__device__ float g_pr[MAXBLOCKS];  // p2 block partials (reg)
__device__ float g_pp[MAXBLOCKS];  // p2 block partials (pos count)
__device__ int   g_count;          // zero-init; reset by p2 last block

__device__ __forceinline__ float warp_red_f(float v) {
    #pragma unroll
    for (int o = 16; o > 0; o >>= 1) v += __shfl_down_sync(0xffffffffu, v, o);
    return v;
}
__device__ __forceinline__ double warp_red_d(double v) {
    #pragma unroll
    for (int o = 16; o > 0; o >>= 1) v += __shfl_down_sync(0xffffffffu, v, o);
    return v;
}

// ---------------- K1 (VERBATIM R10/R11, proven): sliced IoU argmax via atomicMax ----------------
// Rank by r = inter/(areaA+ta): IoU = r/(1-r) strictly increasing in r => same ordering.
// Key = (r_bits & ~0xFF) | (255 - t_global). Negative r -> negative key -> loses signed max.
template <int CTT>
__global__ void __launch_bounds__(TPB, 8)
retina_p1(const float4* __restrict__ anc,
          const float4* __restrict__ tb,
          int A, int Tdyn)
{
    const int t0 = blockIdx.y * (CTT > 0 ? CTT : Tdyn);

    __shared__ float4 s_neg[CTT > 0 ? CTT : MAXT];   // {tz, tw, -tx1, -ty1}
    __shared__ float  s_ta [CTT > 0 ? CTT : MAXT];

    int ccount;
    if (CTT > 0) {
        ccount = CTT;
    } else {
        ccount = Tdyn - t0;
        if (ccount > MAXT) ccount = MAXT;
    }

    for (int t = threadIdx.x; t < ccount; t += TPB) {
        float4 b = tb[t0 + t];
        s_neg[t] = make_float4(b.z, b.w, -b.x, -b.y);
        s_ta[t]  = (b.z - b.x) * (b.w - b.y);
    }
    __syncthreads();

    const int a = blockIdx.x * TPB + threadIdx.x;
    if (a >= A) return;

    const float4 an = anc[a];
    const float az  = an.z,  aw = an.w;
    const float nax = -an.x, nay = -an.y;
    const float areaA = (an.z - an.x) * (an.w - an.y);
    const int idxbase = 255 - t0;

    int best = 0;
    #pragma unroll
    for (int tt = 0; tt < (CTT > 0 ? CTT : MAXT); ++tt) {
        if (CTT == 0 && tt >= ccount) break;
        float4 q = s_neg[tt];
        float ta = s_ta[tt];
        float m1 = fminf(az,  q.x);
        float m2 = fminf(aw,  q.y);
        float n1 = fminf(nax, q.z);          // = -max(ax, tx1)
        float n2 = fminf(nay, q.w);          // = -max(ay, ty1)
        float w  = fmaxf(m1 + n1, 0.f);
        float h  = m2 + n2;
        float inter = w * h;                 // <=0 never wins (key <= 0)
        float S  = areaA + ta;               // RCP off the min/max chain
        float r  = __fdividef(inter, S);     // rank-equivalent to IoU
        int key = (__float_as_int(r) & 0xFFFFFF00) | (idxbase - tt);
        best = max(best, key);
    }
    atomicMax(&g_key[a], best);              // deterministic merge
}

// ---- K2: stage 256x21 cls slab in smem (coalesced), decode winner, full focal,
//          exact IoU, regression, FINAL combine ----
__global__ void __launch_bounds__(TPB)
retina_p2(const float* __restrict__ cls,
          const float4* __restrict__ box,
          const float4* __restrict__ anc,
          const float4* __restrict__ tb,
          const int* __restrict__ tl,
          float* __restrict__ out,
          int A, int T, int N)
{
    __shared__ float4 s_org[MAXT];
    __shared__ float  s_ta[MAXT];
    __shared__ int    s_tl[MAXT];
    __shared__ float  s_cls[TPB * CLASSES];          // 21504 B, contiguous slab

    for (int t = threadIdx.x; t < T; t += TPB) {
        float4 b = tb[t];
        s_org[t] = b;
        s_ta[t]  = (b.z - b.x) * (b.w - b.y);
        s_tl[t]  = tl[t];
    }

    // cooperative coalesced staging of this block's cls slab
    {
        const int cbase = blockIdx.x * (TPB * CLASSES);
        if (cbase + TPB * CLASSES <= N) {
            const float4* src = reinterpret_cast<const float4*>(cls + cbase);
            float4* dst = reinterpret_cast<float4*>(s_cls);
            #pragma unroll
            for (int i = threadIdx.x; i < (TPB * CLASSES) / 4; i += TPB)
                dst[i] = src[i];
        } else {
            for (int i = threadIdx.x; i < TPB * CLASSES; i += TPB) {
                int e = cbase + i;
                s_cls[i] = (e < N) ? cls[e] : -100.f;   // contributes 0 to focal
            }
        }
    }
    __syncthreads();

    const int a = blockIdx.x * TPB + threadIdx.x;
    float cls_sum = 0.f, reg_sum = 0.f, posf = 0.f;

    if (a < A) {
        int key = g_key[a];
        g_key[a] = 0;                         // reset for next run/replay
        int tsel = 255 - (key & 0xFF);
        if (tsel >= T) tsel = 0;              // all-zero corner: argmax = 0, pos = false

        float4 an = anc[a];
        float4 tg = s_org[tsel];
        float areaA = (an.z - an.x) * (an.w - an.y);
        float w = fmaxf(fminf(an.z, tg.z) - fmaxf(an.x, tg.x), 0.f);
        float h = fmaxf(fminf(an.w, tg.w) - fmaxf(an.y, tg.y), 0.f);
        float inter = w * h;
        float uni   = areaA + s_ta[tsel] - inter;
        float iou   = __fdiv_rn(inter, fmaxf(uni, 1e-8f));
        const bool pos = (iou >= 0.5f);
        posf = pos ? 1.f : 0.f;
        const int lbl = pos ? s_tl[tsel] : 0; // background -> class 0 (one_hot(0))

        // ---- focal loss over 21 classes from shared (R6/R7-proven formula) ----
        // bank map i*21+c mod 32: 21 odd => permutation across threads, conflict-free
        const int base = threadIdx.x * CLASSES;
        #pragma unroll
        for (int c = 0; c < CLASSES; ++c) {
            float x = s_cls[base + c];
            bool tgt = (c == lbl);
            float z = tgt ? x : -x;
            float e   = __expf(-fabsf(z));
            float l1p = __logf(1.f + e);
            float ce  = l1p + fmaxf(-z, 0.f);        // softplus(-z)
            float rc  = __fdividef(1.f, 1.f + e);
            float q   = (z >= 0.f) ? e * rc : rc;    // sigmoid(-z) = 1 - pt
            float alpha = tgt ? 0.25f : 0.75f;
            cls_sum += alpha * q * q * ce;
        }

        if (pos) {
            float4 bp = box[a];
            float awx = an.z - an.x, awy = an.w - an.y;
            float acx = (an.x + an.z) * 0.5f, acy = (an.y + an.w) * 0.5f;

            float ep0 = __fdiv_rn((bp.x + bp.z) * 0.5f - acx, awx);
            float ep1 = __fdiv_rn((bp.y + bp.w) * 0.5f - acy, awy);
            float ep2 = logf(__fdiv_rn(bp.z - bp.x, awx));
            float ep3 = logf(__fdiv_rn(bp.w - bp.y, awy));

            float et0 = __fdiv_rn((tg.x + tg.z) * 0.5f - acx, awx);
            float et1 = __fdiv_rn((tg.y + tg.w) * 0.5f - acy, awy);
            float et2 = logf(__fdiv_rn(tg.z - tg.x, awx));
            float et3 = logf(__fdiv_rn(tg.w - tg.y, awy));

            float d;
            d = fabsf(ep0 - et0); reg_sum += (d < 1.f) ? 0.5f * d * d : d - 0.5f;
            d = fabsf(ep1 - et1); reg_sum += (d < 1.f) ? 0.5f * d * d : d - 0.5f;
            d = fabsf(ep2 - et2); reg_sum += (d < 1.f) ? 0.5f * d * d : d - 0.5f;
            d = fabsf(ep3 - et3); reg_sum += (d < 1.f) ? 0.5f * d * d : d - 0.5f;
        }
    }

    // ---- deterministic block reduction ----
    __shared__ float red_c[8], red_r[8], red_p[8];
    float vc = warp_red_f(cls_sum);
    float vr = warp_red_f(reg_sum);
    float vp = warp_red_f(posf);
    int wid = threadIdx.x >> 5, lid = threadIdx.x & 31;
    if (lid == 0) { red_c[wid] = vc; red_r[wid] = vr; red_p[wid] = vp; }
    __syncthreads();
    if (wid == 0) {
        float c2 = (lid < 8) ? red_c[lid] : 0.f;
        float r2 = (lid < 8) ? red_r[lid] : 0.f;
        float p2 = (lid < 8) ? red_p[lid] : 0.f;
        c2 = warp_red_f(c2);
        r2 = warp_red_f(r2);
        p2 = warp_red_f(p2);
        if (lid == 0) {
            g_pc[blockIdx.x] = c2;
            g_pr[blockIdx.x] = r2;
            g_pp[blockIdx.x] = p2;
        }
    }

    // ---- last-block final combine ----
    __shared__ int s_last;
    if (threadIdx.x == 0) {
        __threadfence();
        int prev = atomicAdd(&g_count, 1);
        s_last = (prev == (int)gridDim.x - 1) ? 1 : 0;
    }
    __syncthreads();
    if (s_last) {
        double c = 0.0, r = 0.0, p = 0.0;
        for (int i = threadIdx.x; i < (int)gridDim.x; i += TPB) {
            c += (double)g_pc[i];
            r += (double)g_pr[i];
            p += (double)g_pp[i];
        }
        c = warp_red_d(c);
        r = warp_red_d(r);
        p = warp_red_d(p);
        __shared__ double sc[8], sr[8], sp[8];
        if (lid == 0) { sc[wid] = c; sr[wid] = r; sp[wid] = p; }
        __syncthreads();
        if (threadIdx.x == 0) {
            double tc = 0.0, tr = 0.0, tp = 0.0;
            #pragma unroll
            for (int i = 0; i < 8; ++i) { tc += sc[i]; tr += sr[i]; tp += sp[i]; }
            float pos_cnt = (float)tp;
            float norm = fmaxf(pos_cnt, 1.f);
            float cls_loss = (float)tc / norm;
            float reg_loss = (pos_cnt > 0.f) ? ((float)tr / (norm * 4.f)) : 0.f;
            out[0] = cls_loss + reg_loss;
            out[1] = cls_loss;
            out[2] = reg_loss;
            g_count = 0;
        }
    }
}

extern "C" void kernel_launch(void* const* d_in, const int* in_sizes, int n_in,
                              void* d_out, int out_size)
{
    const float*  cls = (const float*)d_in[0];
    const float4* box = (const float4*)d_in[1];
    const float4* anc = (const float4*)d_in[2];
    const float4* tb  = (const float4*)d_in[3];
    const int*    tl  = (const int*)d_in[4];
    float* out = (float*)d_out;

    int A = in_sizes[2] / 4;       // flattened anchors (B*A)
    int T = in_sizes[4];           // flattened targets (B*T)
    int N = in_sizes[0];           // A * CLASSES
    if (T > 255) T = 255;
    if (A > MAXA) A = MAXA;

    int gx = (A + TPB - 1) / TPB;                 // 768
    if (gx > MAXBLOCKS) gx = MAXBLOCKS;

    if (T == 200) {
        dim3 g1(gx, 4);                           // 4 slices x 50 targets
        retina_p1<50><<<g1, TPB>>>(anc, tb, A, T);
    } else {
        dim3 g1(gx, 1);
        retina_p1<0><<<g1, TPB>>>(anc, tb, A, T);
    }
    retina_p2<<<gx, TPB>>>(cls, box, anc, tb, tl, out, A, T, N);
}